// round 1
// baseline (speedup 1.0000x reference)
#include <cuda_runtime.h>
#include <math.h>

#define N_NODES 100000
#define N_EDGES 600000
#define D 128
#define NGRAPH 64
#define NUM_LAYER 3

// ---------------- scratch (static device globals; no allocation) ----------------
__device__ float g_bufA[(size_t)N_NODES * D];
__device__ float g_bufB[(size_t)N_NODES * D];
__device__ float g_in0[(size_t)N_NODES * D];
__device__ float g_in1[(size_t)N_NODES * D];
__device__ int   g_gstart[NGRAPH + 1];

// ---------------- node input embedding: h = type_emb[x0] + output_emb[x1] -------
__global__ void embed_kernel(const int* __restrict__ x,
                             const float* __restrict__ type_emb,
                             const float* __restrict__ output_emb,
                             float* __restrict__ h) {
    int tid = blockIdx.x * blockDim.x + threadIdx.x;   // N_NODES * 32 lanes of float4
    int node = tid >> 5;
    int c = tid & 31;
    if (node >= N_NODES) return;
    int t = x[node * 2 + 0];
    int o = x[node * 2 + 1];
    float4 a = ((const float4*)(type_emb + (size_t)t * D))[c];
    float4 b = ((const float4*)(output_emb + (size_t)o * D))[c];
    float4 r = make_float4(a.x + b.x, a.y + b.y, a.z + b.z, a.w + b.w);
    ((float4*)(h + (size_t)node * D))[c] = r;
}

// ---------------- duplicate h into both agg buffers (agg init = h, GIN eps=0) ---
__global__ void dup_kernel(const float* __restrict__ h,
                           float* __restrict__ o0, float* __restrict__ o1) {
    int tid = blockIdx.x * blockDim.x + threadIdx.x;   // N_NODES*32 float4 elements
    if (tid >= N_NODES * 32) return;
    float4 v = ((const float4*)h)[tid];
    ((float4*)o0)[tid] = v;
    ((float4*)o1)[tid] = v;
}

// ---------------- scatter-add: agg[dst] += h[src]; one warp per edge ------------
__global__ void scatter_kernel(const float* __restrict__ h,
                               const int* __restrict__ ei,
                               float* __restrict__ agg) {
    int gw = (blockIdx.x * blockDim.x + threadIdx.x) >> 5;
    int lane = threadIdx.x & 31;
    if (gw >= N_EDGES) return;
    int src = ei[gw];
    int dst = ei[N_EDGES + gw];
    float4 v = ((const float4*)(h + (size_t)src * D))[lane];
    float* p = agg + (size_t)dst * D + lane * 4;
    asm volatile("red.global.add.v4.f32 [%0], {%1,%2,%3,%4};"
                 :: "l"(p), "f"(v.x), "f"(v.y), "f"(v.z), "f"(v.w) : "memory");
}

// ---------------- fused GIN MLP: out (+)= relu?( relu(in@W1+b1)@W2 + b2 ) -------
#define TILE_R 64
#define SSTRIDE 132
#define SMEM_BYTES ((D*D*2 + TILE_R*SSTRIDE*2) * 4)

__global__ void __launch_bounds__(256, 1)
gin_mlp_kernel(const float* __restrict__ in,
               const float* __restrict__ w1, const float* __restrict__ b1,
               const float* __restrict__ w2, const float* __restrict__ b2,
               float* __restrict__ out, int accumulate, int relu_out) {
    extern __shared__ float sm[];
    float* sW1 = sm;                       // 128x128
    float* sW2 = sW1 + D * D;              // 128x128
    float* sIn = sW2 + D * D;              // 64 x 132 (padded)
    float* sZ  = sIn + TILE_R * SSTRIDE;   // 64 x 132 (padded)

    int t = threadIdx.x;
    int row0 = blockIdx.x * TILE_R;

    // load both weight matrices (float4 copies)
    {
        const float4* w1v = (const float4*)w1;
        const float4* w2v = (const float4*)w2;
        float4* s1 = (float4*)sW1;
        float4* s2 = (float4*)sW2;
#pragma unroll
        for (int i = 0; i < 16; i++) {
            s1[t + 256 * i] = w1v[t + 256 * i];
            s2[t + 256 * i] = w2v[t + 256 * i];
        }
    }
    // load input tile (zero-fill rows past N_NODES)
    for (int i = t; i < TILE_R * 32; i += 256) {
        int r = i >> 5, c = i & 31;
        int row = row0 + r;
        float4 v = make_float4(0.f, 0.f, 0.f, 0.f);
        if (row < N_NODES) v = ((const float4*)(in + (size_t)row * D))[c];
        *(float4*)&sIn[r * SSTRIDE + c * 4] = v;
    }
    __syncthreads();

    int tr = t >> 4;   // 0..15 -> rows tr*4 .. tr*4+3
    int tc = t & 15;   // 0..15 -> cols tc*8 .. tc*8+7

    float acc[4][8];
    // -------- GEMM1: z = relu(in @ W1 + b1) --------
#pragma unroll
    for (int j = 0; j < 8; j++) {
        float bv = b1[tc * 8 + j];
        acc[0][j] = bv; acc[1][j] = bv; acc[2][j] = bv; acc[3][j] = bv;
    }
#pragma unroll 2
    for (int k = 0; k < D; k += 4) {
        float a[4][4];
#pragma unroll
        for (int r = 0; r < 4; r++) {
            float4 v = *(const float4*)&sIn[(tr * 4 + r) * SSTRIDE + k];
            a[r][0] = v.x; a[r][1] = v.y; a[r][2] = v.z; a[r][3] = v.w;
        }
#pragma unroll
        for (int kk = 0; kk < 4; kk++) {
            float4 w0 = *(const float4*)&sW1[(k + kk) * D + tc * 8];
            float4 w1r = *(const float4*)&sW1[(k + kk) * D + tc * 8 + 4];
#pragma unroll
            for (int r = 0; r < 4; r++) {
                float av = a[r][kk];
                acc[r][0] += av * w0.x;  acc[r][1] += av * w0.y;
                acc[r][2] += av * w0.z;  acc[r][3] += av * w0.w;
                acc[r][4] += av * w1r.x; acc[r][5] += av * w1r.y;
                acc[r][6] += av * w1r.z; acc[r][7] += av * w1r.w;
            }
        }
    }
#pragma unroll
    for (int r = 0; r < 4; r++) {
        float4 lo = make_float4(fmaxf(acc[r][0], 0.f), fmaxf(acc[r][1], 0.f),
                                fmaxf(acc[r][2], 0.f), fmaxf(acc[r][3], 0.f));
        float4 hi = make_float4(fmaxf(acc[r][4], 0.f), fmaxf(acc[r][5], 0.f),
                                fmaxf(acc[r][6], 0.f), fmaxf(acc[r][7], 0.f));
        *(float4*)&sZ[(tr * 4 + r) * SSTRIDE + tc * 8] = lo;
        *(float4*)&sZ[(tr * 4 + r) * SSTRIDE + tc * 8 + 4] = hi;
    }
    __syncthreads();

    // -------- GEMM2: out (+)= z @ W2 + b2 --------
#pragma unroll
    for (int j = 0; j < 8; j++) {
        float bv = b2[tc * 8 + j];
        acc[0][j] = bv; acc[1][j] = bv; acc[2][j] = bv; acc[3][j] = bv;
    }
#pragma unroll 2
    for (int k = 0; k < D; k += 4) {
        float a[4][4];
#pragma unroll
        for (int r = 0; r < 4; r++) {
            float4 v = *(const float4*)&sZ[(tr * 4 + r) * SSTRIDE + k];
            a[r][0] = v.x; a[r][1] = v.y; a[r][2] = v.z; a[r][3] = v.w;
        }
#pragma unroll
        for (int kk = 0; kk < 4; kk++) {
            float4 w0 = *(const float4*)&sW2[(k + kk) * D + tc * 8];
            float4 w1r = *(const float4*)&sW2[(k + kk) * D + tc * 8 + 4];
#pragma unroll
            for (int r = 0; r < 4; r++) {
                float av = a[r][kk];
                acc[r][0] += av * w0.x;  acc[r][1] += av * w0.y;
                acc[r][2] += av * w0.z;  acc[r][3] += av * w0.w;
                acc[r][4] += av * w1r.x; acc[r][5] += av * w1r.y;
                acc[r][6] += av * w1r.z; acc[r][7] += av * w1r.w;
            }
        }
    }
    // epilogue
#pragma unroll
    for (int r = 0; r < 4; r++) {
        int row = row0 + tr * 4 + r;
        if (row >= N_NODES) continue;
        float* op = out + (size_t)row * D + tc * 8;
        float v[8];
#pragma unroll
        for (int j = 0; j < 8; j++) v[j] = acc[r][j];
        if (accumulate) {
            float4 o0 = *(const float4*)(op);
            float4 o1 = *(const float4*)(op + 4);
            v[0] += o0.x; v[1] += o0.y; v[2] += o0.z; v[3] += o0.w;
            v[4] += o1.x; v[5] += o1.y; v[6] += o1.z; v[7] += o1.w;
        }
        if (relu_out) {
#pragma unroll
            for (int j = 0; j < 8; j++) v[j] = fmaxf(v[j], 0.f);
        }
        *(float4*)(op)     = make_float4(v[0], v[1], v[2], v[3]);
        *(float4*)(op + 4) = make_float4(v[4], v[5], v[6], v[7]);
    }
}

// ---------------- graph segment boundaries (batch is sorted) --------------------
__global__ void bounds_kernel(const int* __restrict__ batch) {
    int g = threadIdx.x;
    if (g > NGRAPH) return;
    int lo = 0, hi = N_NODES;
    while (lo < hi) {
        int mid = (lo + hi) >> 1;
        if (batch[mid] < g) lo = mid + 1; else hi = mid;
    }
    g_gstart[g] = lo;
}

// ---------------- pooling: sum/mean/max/min, interleaved output layout ----------
__global__ void pool_kernel(const float* __restrict__ h, float* __restrict__ out,
                            int out_size) {
    int b = blockIdx.x;
    int c = threadIdx.x;                 // dim index 0..127
    int s = g_gstart[b], e = g_gstart[b + 1];
    float s0 = 0.f, s1 = 0.f, s2 = 0.f, s3 = 0.f;
    float mx = -INFINITY, mn = INFINITY;
    int r = s;
    for (; r + 4 <= e; r += 4) {
        float v0 = h[(size_t)(r + 0) * D + c];
        float v1 = h[(size_t)(r + 1) * D + c];
        float v2 = h[(size_t)(r + 2) * D + c];
        float v3 = h[(size_t)(r + 3) * D + c];
        s0 += v0; s1 += v1; s2 += v2; s3 += v3;
        mx = fmaxf(mx, fmaxf(fmaxf(v0, v1), fmaxf(v2, v3)));
        mn = fminf(mn, fminf(fminf(v0, v1), fminf(v2, v3)));
    }
    for (; r < e; r++) {
        float v = h[(size_t)r * D + c];
        s0 += v; mx = fmaxf(mx, v); mn = fminf(mn, v);
    }
    float sum = (s0 + s1) + (s2 + s3);
    float cnt = (float)(e - s);
    float mean = sum / fmaxf(cnt, 1.f);
    float vals[4] = { sum, mean, mx, mn };
    // h_graph[b][j][i] = concat[b][4*i + j]; concat index m = a*128 + c
#pragma unroll
    for (int a = 0; a < 4; a++) {
        int m = a * D + c;
        out[b * 512 + (m & 3) * 128 + (m >> 2)] = vals[a];
    }
    // trailing batch_mask (all true) if the harness packed it into d_out
    if (c < 4) {
        int idx = NGRAPH * 4 * D + b * 4 + c;
        if (idx < out_size) out[idx] = 1.0f;
    }
}

// ---------------- launch ---------------------------------------------------------
extern "C" void kernel_launch(void* const* d_in, const int* in_sizes, int n_in,
                              void* d_out, int out_size) {
    const int*   x          = (const int*)d_in[0];
    const int*   e_pos      = (const int*)d_in[1];
    const int*   e_inv      = (const int*)d_in[2];
    const int*   batch      = (const int*)d_in[3];
    const float* type_emb   = (const float*)d_in[4];
    const float* output_emb = (const float*)d_in[5];
    const float* l1w        = (const float*)d_in[6];
    const float* l1b        = (const float*)d_in[7];
    const float* l2w        = (const float*)d_in[8];
    const float* l2b        = (const float*)d_in[9];
    float* out = (float*)d_out;

    float *hA, *hB, *i0, *i1;
    cudaGetSymbolAddress((void**)&hA, g_bufA);
    cudaGetSymbolAddress((void**)&hB, g_bufB);
    cudaGetSymbolAddress((void**)&i0, g_in0);
    cudaGetSymbolAddress((void**)&i1, g_in1);

    cudaFuncSetAttribute(gin_mlp_kernel,
                         cudaFuncAttributeMaxDynamicSharedMemorySize, SMEM_BYTES);

    embed_kernel<<<(N_NODES * 32 + 255) / 256, 256>>>(x, type_emb, output_emb, hA);

    float* h  = hA;
    float* hn = hB;
    const int gemm_grid = (N_NODES + TILE_R - 1) / TILE_R;   // 1563

    for (int l = 0; l < NUM_LAYER; l++) {
        dup_kernel<<<(N_NODES * 32 + 255) / 256, 256>>>(h, i0, i1);
        scatter_kernel<<<(N_EDGES * 32 + 255) / 256, 256>>>(h, e_pos, i0);
        scatter_kernel<<<(N_EDGES * 32 + 255) / 256, 256>>>(h, e_inv, i1);

        const float* w1p0 = l1w + (size_t)(l * 2 + 0) * D * D;
        const float* w1p1 = l1w + (size_t)(l * 2 + 1) * D * D;
        const float* w2p0 = l2w + (size_t)(l * 2 + 0) * D * D;
        const float* w2p1 = l2w + (size_t)(l * 2 + 1) * D * D;
        const float* b1p0 = l1b + (size_t)(l * 2 + 0) * D;
        const float* b1p1 = l1b + (size_t)(l * 2 + 1) * D;
        const float* b2p0 = l2b + (size_t)(l * 2 + 0) * D;
        const float* b2p1 = l2b + (size_t)(l * 2 + 1) * D;

        gin_mlp_kernel<<<gemm_grid, 256, SMEM_BYTES>>>(
            i0, w1p0, b1p0, w2p0, b2p0, hn, /*accumulate=*/0, /*relu_out=*/0);
        gin_mlp_kernel<<<gemm_grid, 256, SMEM_BYTES>>>(
            i1, w1p1, b1p1, w2p1, b2p1, hn, /*accumulate=*/1,
            /*relu_out=*/(l < NUM_LAYER - 1) ? 1 : 0);

        float* tmp = h; h = hn; hn = tmp;
    }

    bounds_kernel<<<1, NGRAPH + 1>>>(batch);
    pool_kernel<<<NGRAPH, D>>>(h, out, out_size);
}

// round 3
// speedup vs baseline: 1.3135x; 1.3135x over previous
#include <cuda_runtime.h>
#include <cuda_bf16.h>
#include <mma.h>
#include <cstdint>
#include <math.h>

using namespace nvcuda;

#define N_NODES 100000
#define N_EDGES 600000
#define D 128
#define NGRAPH 64
#define NUM_LAYER 3

// ---------------- scratch (static device globals; no allocation) ----------------
__device__ float g_bufA[(size_t)N_NODES * D];
__device__ float g_bufB[(size_t)N_NODES * D];
__device__ float g_in0[(size_t)N_NODES * D];
__device__ float g_in1[(size_t)N_NODES * D];
__device__ int   g_gstart[NGRAPH + 1];

// split fp32 pair into bf16 hi plane + bf16 residual plane (packed bf16x2)
__device__ __forceinline__ void split2(float a, float b, uint32_t& hi, uint32_t& lo) {
    __nv_bfloat16 ha = __float2bfloat16(a), hb = __float2bfloat16(b);
    float ra = a - __bfloat162float(ha);
    float rb = b - __bfloat162float(hb);
    __nv_bfloat162 H; H.x = ha; H.y = hb;
    __nv_bfloat162 L; L.x = __float2bfloat16(ra); L.y = __float2bfloat16(rb);
    hi = *(uint32_t*)&H;
    lo = *(uint32_t*)&L;
}

// ---------------- smem layout (bytes) -------------------------------------------
#define SSTRIDE 144                    // elements; 288 B rows (32B aligned)
#define PLANE_BYTES (128 * SSTRIDE * 2)  // 36864
#define SM_B1      0
#define SM_B2      512
#define SM_SCRATCH 1024                // 8 warps x 256 floats = 8192 B
#define SM_AH      (SM_SCRATCH + 8192)
#define SM_AL      (SM_AH + PLANE_BYTES)
#define SM_W1H     (SM_AL + PLANE_BYTES)
#define SM_W1L     (SM_W1H + PLANE_BYTES)
#define SM_W2H     (SM_W1L + PLANE_BYTES)
#define SM_W2L     (SM_W2H + PLANE_BYTES)
#define SM_TOTAL   (SM_W2L + PLANE_BYTES)   // 230400 bytes

// ================= fused GIN MLP via bf16 split-precision WMMA ==================
// out (+)= maybe_relu( relu(in@W1 + b1) @ W2 + b2 )
__global__ void __launch_bounds__(256, 1)
gin_mma_kernel(const float* __restrict__ in,
               const float* __restrict__ w1, const float* __restrict__ b1,
               const float* __restrict__ w2, const float* __restrict__ b2,
               float* __restrict__ out, int accumulate, int relu_out) {
    extern __shared__ char sm[];
    float* b1s = (float*)(sm + SM_B1);
    float* b2s = (float*)(sm + SM_B2);
    __nv_bfloat16* sAh  = (__nv_bfloat16*)(sm + SM_AH);
    __nv_bfloat16* sAl  = (__nv_bfloat16*)(sm + SM_AL);
    __nv_bfloat16* sW1h = (__nv_bfloat16*)(sm + SM_W1H);
    __nv_bfloat16* sW1l = (__nv_bfloat16*)(sm + SM_W1L);
    __nv_bfloat16* sW2h = (__nv_bfloat16*)(sm + SM_W2H);
    __nv_bfloat16* sW2l = (__nv_bfloat16*)(sm + SM_W2L);

    const int tid = threadIdx.x;
    const int wid = tid >> 5;
    const int lane = tid & 31;
    const int row0 = blockIdx.x * 128;

    if (tid < 128) { b1s[tid] = b1[tid]; b2s[tid] = b2[tid]; }

    // ---- A tile: 128 rows fp32 -> bf16 hi/lo planes (row-major, stride 144) ----
    for (int i = tid; i < 128 * 64; i += 256) {
        int m = i >> 6, kp = i & 63;
        int row = row0 + m;
        float2 v = make_float2(0.f, 0.f);
        if (row < N_NODES) v = ((const float2*)(in + (size_t)row * D))[kp];
        uint32_t hi, lo;
        split2(v.x, v.y, hi, lo);
        *(uint32_t*)&sAh[m * SSTRIDE + 2 * kp] = hi;
        *(uint32_t*)&sAl[m * SSTRIDE + 2 * kp] = lo;
    }
    // ---- weights: W[k][n] row-major (matrix_b layout), hi/lo split ----
    for (int i = tid; i < 128 * 64; i += 256) {
        int k = i >> 6, np = i & 63;
        float2 va = ((const float2*)(w1 + (size_t)k * D))[np];
        float2 vb = ((const float2*)(w2 + (size_t)k * D))[np];
        uint32_t h, l;
        split2(va.x, va.y, h, l);
        *(uint32_t*)&sW1h[k * SSTRIDE + 2 * np] = h;
        *(uint32_t*)&sW1l[k * SSTRIDE + 2 * np] = l;
        split2(vb.x, vb.y, h, l);
        *(uint32_t*)&sW2h[k * SSTRIDE + 2 * np] = h;
        *(uint32_t*)&sW2l[k * SSTRIDE + 2 * np] = l;
    }
    __syncthreads();

    float* sw = (float*)(sm + SM_SCRATCH) + wid * 256;   // 16x16 fp32 per warp
    const int m0 = wid * 16;
    const int r = lane >> 1, half = lane & 1;

    wmma::fragment<wmma::accumulator, 16, 16, 16, float> acc[8];

    // =================== GEMM1: D1 = A @ W1 (3 split terms) ===================
#pragma unroll
    for (int nt = 0; nt < 8; nt++) wmma::fill_fragment(acc[nt], 0.f);
    {
        const __nv_bfloat16* APl[3] = { sAh, sAh, sAl };
        const __nv_bfloat16* BPl[3] = { sW1h, sW1l, sW1h };
#pragma unroll
        for (int t3 = 0; t3 < 3; t3++) {
            for (int k = 0; k < 128; k += 16) {
                wmma::fragment<wmma::matrix_a, 16, 16, 16, __nv_bfloat16, wmma::row_major> af;
                wmma::load_matrix_sync(af, APl[t3] + m0 * SSTRIDE + k, SSTRIDE);
#pragma unroll
                for (int nt = 0; nt < 8; nt++) {
                    wmma::fragment<wmma::matrix_b, 16, 16, 16, __nv_bfloat16, wmma::row_major> bf;
                    wmma::load_matrix_sync(bf, BPl[t3] + k * SSTRIDE + nt * 16, SSTRIDE);
                    wmma::mma_sync(acc[nt], af, bf, acc[nt]);
                }
            }
        }
    }
    // ---- epilogue1: z = relu(D1 + b1) -> re-split into A planes (warp-local) ----
#pragma unroll
    for (int nt = 0; nt < 8; nt++) {
        wmma::store_matrix_sync(sw, acc[nt], 16, wmma::mem_row_major);
        __syncwarp();
#pragma unroll
        for (int q = 0; q < 4; q++) {
            int c0 = half * 8 + 2 * q;
            int n0 = nt * 16 + c0;
            float z0 = fmaxf(sw[r * 16 + c0]     + b1s[n0],     0.f);
            float z1 = fmaxf(sw[r * 16 + c0 + 1] + b1s[n0 + 1], 0.f);
            uint32_t hi, lo;
            split2(z0, z1, hi, lo);
            *(uint32_t*)&sAh[(m0 + r) * SSTRIDE + n0] = hi;
            *(uint32_t*)&sAl[(m0 + r) * SSTRIDE + n0] = lo;
        }
        __syncwarp();
    }

    // =================== GEMM2: D2 = Z @ W2 (3 split terms) ===================
#pragma unroll
    for (int nt = 0; nt < 8; nt++) wmma::fill_fragment(acc[nt], 0.f);
    {
        const __nv_bfloat16* APl[3] = { sAh, sAh, sAl };
        const __nv_bfloat16* BPl[3] = { sW2h, sW2l, sW2h };
#pragma unroll
        for (int t3 = 0; t3 < 3; t3++) {
            for (int k = 0; k < 128; k += 16) {
                wmma::fragment<wmma::matrix_a, 16, 16, 16, __nv_bfloat16, wmma::row_major> af;
                wmma::load_matrix_sync(af, APl[t3] + m0 * SSTRIDE + k, SSTRIDE);
#pragma unroll
                for (int nt = 0; nt < 8; nt++) {
                    wmma::fragment<wmma::matrix_b, 16, 16, 16, __nv_bfloat16, wmma::row_major> bf;
                    wmma::load_matrix_sync(bf, BPl[t3] + k * SSTRIDE + nt * 16, SSTRIDE);
                    wmma::mma_sync(acc[nt], af, bf, acc[nt]);
                }
            }
        }
    }
    // ---- epilogue2: out (+)= maybe_relu(D2 + b2) ----
    {
        const int row = row0 + m0 + r;
#pragma unroll
        for (int nt = 0; nt < 8; nt++) {
            wmma::store_matrix_sync(sw, acc[nt], 16, wmma::mem_row_major);
            __syncwarp();
            if (row < N_NODES) {
                int n0 = nt * 16 + half * 8;
                float* op = out + (size_t)row * D + n0;
                float v[8];
#pragma unroll
                for (int j = 0; j < 8; j++) v[j] = sw[r * 16 + half * 8 + j] + b2s[n0 + j];
                if (accumulate) {
                    float4 o0 = *(const float4*)(op);
                    float4 o1 = *(const float4*)(op + 4);
                    v[0] += o0.x; v[1] += o0.y; v[2] += o0.z; v[3] += o0.w;
                    v[4] += o1.x; v[5] += o1.y; v[6] += o1.z; v[7] += o1.w;
                }
                if (relu_out) {
#pragma unroll
                    for (int j = 0; j < 8; j++) v[j] = fmaxf(v[j], 0.f);
                }
                *(float4*)(op)     = make_float4(v[0], v[1], v[2], v[3]);
                *(float4*)(op + 4) = make_float4(v[4], v[5], v[6], v[7]);
            }
            __syncwarp();
        }
    }
}

// ---------------- node input embedding ------------------------------------------
__global__ void embed_kernel(const int* __restrict__ x,
                             const float* __restrict__ type_emb,
                             const float* __restrict__ output_emb,
                             float* __restrict__ h) {
    int tid = blockIdx.x * blockDim.x + threadIdx.x;
    int node = tid >> 5;
    int c = tid & 31;
    if (node >= N_NODES) return;
    int t = x[node * 2 + 0];
    int o = x[node * 2 + 1];
    float4 a = ((const float4*)(type_emb + (size_t)t * D))[c];
    float4 b = ((const float4*)(output_emb + (size_t)o * D))[c];
    ((float4*)(h + (size_t)node * D))[c] =
        make_float4(a.x + b.x, a.y + b.y, a.z + b.z, a.w + b.w);
}

// ---------------- duplicate h into both agg buffers ------------------------------
__global__ void dup_kernel(const float* __restrict__ h,
                           float* __restrict__ o0, float* __restrict__ o1) {
    int tid = blockIdx.x * blockDim.x + threadIdx.x;
    if (tid >= N_NODES * 32) return;
    float4 v = ((const float4*)h)[tid];
    ((float4*)o0)[tid] = v;
    ((float4*)o1)[tid] = v;
}

// ---------------- scatter-add: agg[dst] += h[src] --------------------------------
__global__ void scatter_kernel(const float* __restrict__ h,
                               const int* __restrict__ ei,
                               float* __restrict__ agg) {
    int gw = (blockIdx.x * blockDim.x + threadIdx.x) >> 5;
    int lane = threadIdx.x & 31;
    if (gw >= N_EDGES) return;
    int src = ei[gw];
    int dst = ei[N_EDGES + gw];
    float4 v = ((const float4*)(h + (size_t)src * D))[lane];
    float* p = agg + (size_t)dst * D + lane * 4;
    asm volatile("red.global.add.v4.f32 [%0], {%1,%2,%3,%4};"
                 :: "l"(p), "f"(v.x), "f"(v.y), "f"(v.z), "f"(v.w) : "memory");
}

// ---------------- graph segment boundaries ---------------------------------------
__global__ void bounds_kernel(const int* __restrict__ batch) {
    int g = threadIdx.x;
    if (g > NGRAPH) return;
    int lo = 0, hi = N_NODES;
    while (lo < hi) {
        int mid = (lo + hi) >> 1;
        if (batch[mid] < g) lo = mid + 1; else hi = mid;
    }
    g_gstart[g] = lo;
}

// ---------------- pooling --------------------------------------------------------
__global__ void pool_kernel(const float* __restrict__ h, float* __restrict__ out,
                            int out_size) {
    int b = blockIdx.x;
    int c = threadIdx.x;
    int s = g_gstart[b], e = g_gstart[b + 1];
    float s0 = 0.f, s1 = 0.f, s2 = 0.f, s3 = 0.f;
    float mx = -INFINITY, mn = INFINITY;
    int r = s;
    for (; r + 4 <= e; r += 4) {
        float v0 = h[(size_t)(r + 0) * D + c];
        float v1 = h[(size_t)(r + 1) * D + c];
        float v2 = h[(size_t)(r + 2) * D + c];
        float v3 = h[(size_t)(r + 3) * D + c];
        s0 += v0; s1 += v1; s2 += v2; s3 += v3;
        mx = fmaxf(mx, fmaxf(fmaxf(v0, v1), fmaxf(v2, v3)));
        mn = fminf(mn, fminf(fminf(v0, v1), fminf(v2, v3)));
    }
    for (; r < e; r++) {
        float v = h[(size_t)r * D + c];
        s0 += v; mx = fmaxf(mx, v); mn = fminf(mn, v);
    }
    float sum = (s0 + s1) + (s2 + s3);
    float cnt = (float)(e - s);
    float mean = sum / fmaxf(cnt, 1.f);
    float vals[4] = { sum, mean, mx, mn };
#pragma unroll
    for (int a = 0; a < 4; a++) {
        int m = a * D + c;
        out[b * 512 + (m & 3) * 128 + (m >> 2)] = vals[a];
    }
    if (c < 4) {
        int idx = NGRAPH * 4 * D + b * 4 + c;
        if (idx < out_size) out[idx] = 1.0f;
    }
}

// ---------------- launch ---------------------------------------------------------
extern "C" void kernel_launch(void* const* d_in, const int* in_sizes, int n_in,
                              void* d_out, int out_size) {
    const int*   x          = (const int*)d_in[0];
    const int*   e_pos      = (const int*)d_in[1];
    const int*   e_inv      = (const int*)d_in[2];
    const int*   batch      = (const int*)d_in[3];
    const float* type_emb   = (const float*)d_in[4];
    const float* output_emb = (const float*)d_in[5];
    const float* l1w        = (const float*)d_in[6];
    const float* l1b        = (const float*)d_in[7];
    const float* l2w        = (const float*)d_in[8];
    const float* l2b        = (const float*)d_in[9];
    float* out = (float*)d_out;

    float *hA, *hB, *i0, *i1;
    cudaGetSymbolAddress((void**)&hA, g_bufA);
    cudaGetSymbolAddress((void**)&hB, g_bufB);
    cudaGetSymbolAddress((void**)&i0, g_in0);
    cudaGetSymbolAddress((void**)&i1, g_in1);

    cudaFuncSetAttribute(gin_mma_kernel,
                         cudaFuncAttributeMaxDynamicSharedMemorySize, SM_TOTAL);

    embed_kernel<<<(N_NODES * 32 + 255) / 256, 256>>>(x, type_emb, output_emb, hA);

    float* h  = hA;
    float* hn = hB;
    const int gemm_grid = (N_NODES + 127) / 128;   // 782

    for (int l = 0; l < NUM_LAYER; l++) {
        dup_kernel<<<(N_NODES * 32 + 255) / 256, 256>>>(h, i0, i1);
        scatter_kernel<<<(N_EDGES * 32 + 255) / 256, 256>>>(h, e_pos, i0);
        scatter_kernel<<<(N_EDGES * 32 + 255) / 256, 256>>>(h, e_inv, i1);

        const float* w1p0 = l1w + (size_t)(l * 2 + 0) * D * D;
        const float* w1p1 = l1w + (size_t)(l * 2 + 1) * D * D;
        const float* w2p0 = l2w + (size_t)(l * 2 + 0) * D * D;
        const float* w2p1 = l2w + (size_t)(l * 2 + 1) * D * D;
        const float* b1p0 = l1b + (size_t)(l * 2 + 0) * D;
        const float* b1p1 = l1b + (size_t)(l * 2 + 1) * D;
        const float* b2p0 = l2b + (size_t)(l * 2 + 0) * D;
        const float* b2p1 = l2b + (size_t)(l * 2 + 1) * D;

        gin_mma_kernel<<<gemm_grid, 256, SM_TOTAL>>>(
            i0, w1p0, b1p0, w2p0, b2p0, hn, /*accumulate=*/0, /*relu_out=*/0);
        gin_mma_kernel<<<gemm_grid, 256, SM_TOTAL>>>(
            i1, w1p1, b1p1, w2p1, b2p1, hn, /*accumulate=*/1,
            /*relu_out=*/(l < NUM_LAYER - 1) ? 1 : 0);

        float* tmp = h; h = hn; hn = tmp;
    }

    bounds_kernel<<<1, NGRAPH + 1>>>(batch);
    pool_kernel<<<NGRAPH, D>>>(h, out, out_size);
}

// round 4
// speedup vs baseline: 1.8554x; 1.4126x over previous
#include <cuda_runtime.h>
#include <cuda_bf16.h>
#include <mma.h>
#include <cstdint>
#include <math.h>

using namespace nvcuda;

#define N_NODES 100000
#define N_EDGES 600000
#define D 128
#define NGRAPH 64
#define NUM_LAYER 3

// ---------------- scratch (static device globals; no allocation) ----------------
__device__ float g_bufA[(size_t)N_NODES * D];
__device__ float g_bufB[(size_t)N_NODES * D];
__device__ float g_in0[(size_t)N_NODES * D];
__device__ float g_in1[(size_t)N_NODES * D];
__device__ int   g_gstart[NGRAPH + 1];
// CSR scratch (2 relations)
__device__ int g_rowptr[2][N_NODES + 1];
__device__ int g_cursor[2][N_NODES];
__device__ int g_csrsrc[2][N_EDGES];
__device__ int g_bsums[2][512];

// split fp32 pair into bf16 hi plane + bf16 residual plane (packed bf16x2)
__device__ __forceinline__ void split2(float a, float b, uint32_t& hi, uint32_t& lo) {
    __nv_bfloat16 ha = __float2bfloat16(a), hb = __float2bfloat16(b);
    float ra = a - __bfloat162float(ha);
    float rb = b - __bfloat162float(hb);
    __nv_bfloat162 H; H.x = ha; H.y = hb;
    __nv_bfloat162 L; L.x = __float2bfloat16(ra); L.y = __float2bfloat16(rb);
    hi = *(uint32_t*)&H;
    lo = *(uint32_t*)&L;
}

// ---------------- smem layout (bytes) -------------------------------------------
#define SSTRIDE 144                      // elements; 288 B rows
#define PLANE_BYTES (128 * SSTRIDE * 2)  // 36864
#define SM_B1      0
#define SM_B2      512
#define SM_SCRATCH 1024                  // 8 warps x 256 floats = 8192 B
#define SM_AH      (SM_SCRATCH + 8192)
#define SM_AL      (SM_AH + PLANE_BYTES)
#define SM_W1H     (SM_AL + PLANE_BYTES)
#define SM_W1L     (SM_W1H + PLANE_BYTES)
#define SM_W2H     (SM_W1L + PLANE_BYTES)
#define SM_W2L     (SM_W2H + PLANE_BYTES)
#define SM_TOTAL   (SM_W2L + PLANE_BYTES)   // 230400 bytes

typedef wmma::fragment<wmma::matrix_a, 16, 16, 16, __nv_bfloat16, wmma::row_major> AFrag;
typedef wmma::fragment<wmma::matrix_b, 16, 16, 16, __nv_bfloat16, wmma::row_major> BFrag;
typedef wmma::fragment<wmma::accumulator, 16, 16, 16, float> CFrag;

// ================= fused GIN MLP via bf16 split-precision WMMA ==================
// out (+)= maybe_relu( relu(in@W1 + b1) @ W2 + b2 )
__global__ void __launch_bounds__(256, 1)
gin_mma_kernel(const float* __restrict__ in,
               const float* __restrict__ w1, const float* __restrict__ b1,
               const float* __restrict__ w2, const float* __restrict__ b2,
               float* __restrict__ out, int accumulate, int relu_out) {
    extern __shared__ char sm[];
    float* b1s = (float*)(sm + SM_B1);
    float* b2s = (float*)(sm + SM_B2);
    __nv_bfloat16* sAh  = (__nv_bfloat16*)(sm + SM_AH);
    __nv_bfloat16* sAl  = (__nv_bfloat16*)(sm + SM_AL);
    __nv_bfloat16* sW1h = (__nv_bfloat16*)(sm + SM_W1H);
    __nv_bfloat16* sW1l = (__nv_bfloat16*)(sm + SM_W1L);
    __nv_bfloat16* sW2h = (__nv_bfloat16*)(sm + SM_W2H);
    __nv_bfloat16* sW2l = (__nv_bfloat16*)(sm + SM_W2L);

    const int tid = threadIdx.x;
    const int wid = tid >> 5;
    const int lane = tid & 31;
    const int row0 = blockIdx.x * 128;

    if (tid < 128) { b1s[tid] = b1[tid]; b2s[tid] = b2[tid]; }

    // ---- A tile: 128 rows fp32 -> bf16 hi/lo planes ----
    for (int i = tid; i < 128 * 64; i += 256) {
        int m = i >> 6, kp = i & 63;
        int row = row0 + m;
        float2 v = make_float2(0.f, 0.f);
        if (row < N_NODES) v = ((const float2*)(in + (size_t)row * D))[kp];
        uint32_t hi, lo;
        split2(v.x, v.y, hi, lo);
        *(uint32_t*)&sAh[m * SSTRIDE + 2 * kp] = hi;
        *(uint32_t*)&sAl[m * SSTRIDE + 2 * kp] = lo;
    }
    // ---- weights: W[k][n] row-major (matrix_b layout), hi/lo split ----
    for (int i = tid; i < 128 * 64; i += 256) {
        int k = i >> 6, np = i & 63;
        float2 va = ((const float2*)(w1 + (size_t)k * D))[np];
        float2 vb = ((const float2*)(w2 + (size_t)k * D))[np];
        uint32_t h, l;
        split2(va.x, va.y, h, l);
        *(uint32_t*)&sW1h[k * SSTRIDE + 2 * np] = h;
        *(uint32_t*)&sW1l[k * SSTRIDE + 2 * np] = l;
        split2(vb.x, vb.y, h, l);
        *(uint32_t*)&sW2h[k * SSTRIDE + 2 * np] = h;
        *(uint32_t*)&sW2l[k * SSTRIDE + 2 * np] = l;
    }
    __syncthreads();

    // warp tiling: 4 warps in M (32 rows each), 2 warps in N (64 cols each)
    const int mwarp = wid >> 1;
    const int nwarp = wid & 1;
    const int m0 = mwarp * 32;
    const int n0w = nwarp * 64;
    float* sw = (float*)(sm + SM_SCRATCH) + wid * 256;   // 16x16 fp32 per warp
    const int r = lane >> 1, half = lane & 1;

    CFrag acc[2][4];

    // =================== GEMM1: D1 = A @ W1 (3 split terms) ===================
#pragma unroll
    for (int mt = 0; mt < 2; mt++)
#pragma unroll
        for (int nt = 0; nt < 4; nt++) wmma::fill_fragment(acc[mt][nt], 0.f);

    for (int k = 0; k < 128; k += 16) {
        AFrag ah[2], al[2];
#pragma unroll
        for (int mt = 0; mt < 2; mt++) {
            wmma::load_matrix_sync(ah[mt], sAh + (m0 + mt * 16) * SSTRIDE + k, SSTRIDE);
            wmma::load_matrix_sync(al[mt], sAl + (m0 + mt * 16) * SSTRIDE + k, SSTRIDE);
        }
#pragma unroll
        for (int nt = 0; nt < 4; nt++) {
            BFrag bh, bl;
            wmma::load_matrix_sync(bh, sW1h + k * SSTRIDE + n0w + nt * 16, SSTRIDE);
            wmma::load_matrix_sync(bl, sW1l + k * SSTRIDE + n0w + nt * 16, SSTRIDE);
#pragma unroll
            for (int mt = 0; mt < 2; mt++) {
                wmma::mma_sync(acc[mt][nt], ah[mt], bh, acc[mt][nt]);
                wmma::mma_sync(acc[mt][nt], ah[mt], bl, acc[mt][nt]);
                wmma::mma_sync(acc[mt][nt], al[mt], bh, acc[mt][nt]);
            }
        }
    }
    __syncthreads();   // all warps done reading A planes before overwrite

    // ---- epilogue1: z = relu(D1 + b1) -> re-split into A planes ----
#pragma unroll
    for (int mt = 0; mt < 2; mt++) {
#pragma unroll
        for (int nt = 0; nt < 4; nt++) {
            wmma::store_matrix_sync(sw, acc[mt][nt], 16, wmma::mem_row_major);
            __syncwarp();
#pragma unroll
            for (int q = 0; q < 4; q++) {
                int c0 = half * 8 + 2 * q;
                int n0 = n0w + nt * 16 + c0;
                float z0 = fmaxf(sw[r * 16 + c0]     + b1s[n0],     0.f);
                float z1 = fmaxf(sw[r * 16 + c0 + 1] + b1s[n0 + 1], 0.f);
                uint32_t hi, lo;
                split2(z0, z1, hi, lo);
                int mrow = m0 + mt * 16 + r;
                *(uint32_t*)&sAh[mrow * SSTRIDE + n0] = hi;
                *(uint32_t*)&sAl[mrow * SSTRIDE + n0] = lo;
            }
            __syncwarp();
        }
    }
    __syncthreads();   // full Z tile visible to all warps

    // =================== GEMM2: D2 = Z @ W2 (3 split terms) ===================
#pragma unroll
    for (int mt = 0; mt < 2; mt++)
#pragma unroll
        for (int nt = 0; nt < 4; nt++) wmma::fill_fragment(acc[mt][nt], 0.f);

    for (int k = 0; k < 128; k += 16) {
        AFrag ah[2], al[2];
#pragma unroll
        for (int mt = 0; mt < 2; mt++) {
            wmma::load_matrix_sync(ah[mt], sAh + (m0 + mt * 16) * SSTRIDE + k, SSTRIDE);
            wmma::load_matrix_sync(al[mt], sAl + (m0 + mt * 16) * SSTRIDE + k, SSTRIDE);
        }
#pragma unroll
        for (int nt = 0; nt < 4; nt++) {
            BFrag bh, bl;
            wmma::load_matrix_sync(bh, sW2h + k * SSTRIDE + n0w + nt * 16, SSTRIDE);
            wmma::load_matrix_sync(bl, sW2l + k * SSTRIDE + n0w + nt * 16, SSTRIDE);
#pragma unroll
            for (int mt = 0; mt < 2; mt++) {
                wmma::mma_sync(acc[mt][nt], ah[mt], bh, acc[mt][nt]);
                wmma::mma_sync(acc[mt][nt], ah[mt], bl, acc[mt][nt]);
                wmma::mma_sync(acc[mt][nt], al[mt], bh, acc[mt][nt]);
            }
        }
    }

    // ---- epilogue2: out (+)= maybe_relu(D2 + b2) ----
#pragma unroll
    for (int mt = 0; mt < 2; mt++) {
        const int row = row0 + m0 + mt * 16 + r;
#pragma unroll
        for (int nt = 0; nt < 4; nt++) {
            wmma::store_matrix_sync(sw, acc[mt][nt], 16, wmma::mem_row_major);
            __syncwarp();
            if (row < N_NODES) {
                int n0 = n0w + nt * 16 + half * 8;
                float* op = out + (size_t)row * D + n0;
                float v[8];
#pragma unroll
                for (int j = 0; j < 8; j++) v[j] = sw[r * 16 + half * 8 + j] + b2s[n0 + j];
                if (accumulate) {
                    float4 o0 = *(const float4*)(op);
                    float4 o1 = *(const float4*)(op + 4);
                    v[0] += o0.x; v[1] += o0.y; v[2] += o0.z; v[3] += o0.w;
                    v[4] += o1.x; v[5] += o1.y; v[6] += o1.z; v[7] += o1.w;
                }
                if (relu_out) {
#pragma unroll
                    for (int j = 0; j < 8; j++) v[j] = fmaxf(v[j], 0.f);
                }
                *(float4*)(op)     = make_float4(v[0], v[1], v[2], v[3]);
                *(float4*)(op + 4) = make_float4(v[4], v[5], v[6], v[7]);
            }
            __syncwarp();
        }
    }
}

// ---------------- node input embedding ------------------------------------------
__global__ void embed_kernel(const int* __restrict__ x,
                             const float* __restrict__ type_emb,
                             const float* __restrict__ output_emb,
                             float* __restrict__ h) {
    int tid = blockIdx.x * blockDim.x + threadIdx.x;
    int node = tid >> 5;
    int c = tid & 31;
    if (node >= N_NODES) return;
    int t = x[node * 2 + 0];
    int o = x[node * 2 + 1];
    float4 a = ((const float4*)(type_emb + (size_t)t * D))[c];
    float4 b = ((const float4*)(output_emb + (size_t)o * D))[c];
    ((float4*)(h + (size_t)node * D))[c] =
        make_float4(a.x + b.x, a.y + b.y, a.z + b.z, a.w + b.w);
}

// ---------------- CSR build -------------------------------------------------------
__global__ void hist_kernel(const int* __restrict__ ei, int* __restrict__ rowptr) {
    int e = blockIdx.x * blockDim.x + threadIdx.x;
    if (e >= N_EDGES) return;
    atomicAdd(&rowptr[ei[N_EDGES + e] + 1], 1);
}
__global__ void scan1_kernel(int* __restrict__ rowptr, int* __restrict__ bsums) {
    __shared__ int s[256];
    int idx = blockIdx.x * 256 + threadIdx.x;
    int v = (idx < N_NODES) ? rowptr[idx + 1] : 0;
    s[threadIdx.x] = v;
    __syncthreads();
#pragma unroll
    for (int o = 1; o < 256; o <<= 1) {
        int t = (threadIdx.x >= o) ? s[threadIdx.x - o] : 0;
        __syncthreads();
        s[threadIdx.x] += t;
        __syncthreads();
    }
    if (idx < N_NODES) rowptr[idx + 1] = s[threadIdx.x];
    if (threadIdx.x == 255) bsums[blockIdx.x] = s[255];
}
__global__ void scan2_kernel(int* __restrict__ bsums, int nb) {
    __shared__ int s[512];
    int t = threadIdx.x;
    int v = (t < nb) ? bsums[t] : 0;
    s[t] = v;
    __syncthreads();
#pragma unroll
    for (int o = 1; o < 512; o <<= 1) {
        int x = (t >= o) ? s[t - o] : 0;
        __syncthreads();
        s[t] += x;
        __syncthreads();
    }
    if (t < nb) bsums[t] = s[t] - v;   // exclusive prefix
}
__global__ void scan3_kernel(int* __restrict__ rowptr, const int* __restrict__ bsums) {
    int idx = blockIdx.x * 256 + threadIdx.x;
    if (idx < N_NODES) rowptr[idx + 1] += bsums[blockIdx.x];
}
__global__ void fill_kernel(const int* __restrict__ ei, int* __restrict__ cursor,
                            int* __restrict__ csrsrc) {
    int e = blockIdx.x * blockDim.x + threadIdx.x;
    if (e >= N_EDGES) return;
    int src = ei[e];
    int dst = ei[N_EDGES + e];
    int pos = atomicAdd(&cursor[dst], 1);
    csrsrc[pos] = src;
}

// ---------------- gather aggregation: agg[n] = h[n] + sum_{src in N(n)} h[src] ---
__global__ void gather_kernel(const float* __restrict__ h,
                              const int* __restrict__ rowptr,
                              const int* __restrict__ csrsrc,
                              float* __restrict__ agg) {
    int warp = (blockIdx.x * blockDim.x + threadIdx.x) >> 5;
    int lane = threadIdx.x & 31;
    if (warp >= N_NODES) return;
    int s = rowptr[warp], e = rowptr[warp + 1];
    float4 acc = ((const float4*)(h + (size_t)warp * D))[lane];
    for (int i = s; i < e; i++) {
        int src = csrsrc[i];
        float4 v = ((const float4*)(h + (size_t)src * D))[lane];
        acc.x += v.x; acc.y += v.y; acc.z += v.z; acc.w += v.w;
    }
    ((float4*)(agg + (size_t)warp * D))[lane] = acc;
}

// ---------------- graph segment boundaries ---------------------------------------
__global__ void bounds_kernel(const int* __restrict__ batch) {
    int g = threadIdx.x;
    if (g > NGRAPH) return;
    int lo = 0, hi = N_NODES;
    while (lo < hi) {
        int mid = (lo + hi) >> 1;
        if (batch[mid] < g) lo = mid + 1; else hi = mid;
    }
    g_gstart[g] = lo;
}

// ---------------- pooling --------------------------------------------------------
__global__ void pool_kernel(const float* __restrict__ h, float* __restrict__ out,
                            int out_size) {
    int b = blockIdx.x;
    int c = threadIdx.x;
    int s = g_gstart[b], e = g_gstart[b + 1];
    float s0 = 0.f, s1 = 0.f, s2 = 0.f, s3 = 0.f;
    float mx = -INFINITY, mn = INFINITY;
    int r = s;
    for (; r + 4 <= e; r += 4) {
        float v0 = h[(size_t)(r + 0) * D + c];
        float v1 = h[(size_t)(r + 1) * D + c];
        float v2 = h[(size_t)(r + 2) * D + c];
        float v3 = h[(size_t)(r + 3) * D + c];
        s0 += v0; s1 += v1; s2 += v2; s3 += v3;
        mx = fmaxf(mx, fmaxf(fmaxf(v0, v1), fmaxf(v2, v3)));
        mn = fminf(mn, fminf(fminf(v0, v1), fminf(v2, v3)));
    }
    for (; r < e; r++) {
        float v = h[(size_t)r * D + c];
        s0 += v; mx = fmaxf(mx, v); mn = fminf(mn, v);
    }
    float sum = (s0 + s1) + (s2 + s3);
    float cnt = (float)(e - s);
    float mean = sum / fmaxf(cnt, 1.f);
    float vals[4] = { sum, mean, mx, mn };
#pragma unroll
    for (int a = 0; a < 4; a++) {
        int m = a * D + c;
        out[b * 512 + (m & 3) * 128 + (m >> 2)] = vals[a];
    }
    if (c < 4) {
        int idx = NGRAPH * 4 * D + b * 4 + c;
        if (idx < out_size) out[idx] = 1.0f;
    }
}

// ---------------- launch ---------------------------------------------------------
extern "C" void kernel_launch(void* const* d_in, const int* in_sizes, int n_in,
                              void* d_out, int out_size) {
    const int*   x          = (const int*)d_in[0];
    const int*   e_pos      = (const int*)d_in[1];
    const int*   e_inv      = (const int*)d_in[2];
    const int*   batch      = (const int*)d_in[3];
    const float* type_emb   = (const float*)d_in[4];
    const float* output_emb = (const float*)d_in[5];
    const float* l1w        = (const float*)d_in[6];
    const float* l1b        = (const float*)d_in[7];
    const float* l2w        = (const float*)d_in[8];
    const float* l2b        = (const float*)d_in[9];
    float* out = (float*)d_out;

    float *hA, *hB, *i0, *i1;
    int *rowptr, *cursor, *csrsrc, *bsums;
    cudaGetSymbolAddress((void**)&hA, g_bufA);
    cudaGetSymbolAddress((void**)&hB, g_bufB);
    cudaGetSymbolAddress((void**)&i0, g_in0);
    cudaGetSymbolAddress((void**)&i1, g_in1);
    cudaGetSymbolAddress((void**)&rowptr, g_rowptr);
    cudaGetSymbolAddress((void**)&cursor, g_cursor);
    cudaGetSymbolAddress((void**)&csrsrc, g_csrsrc);
    cudaGetSymbolAddress((void**)&bsums, g_bsums);

    cudaFuncSetAttribute(gin_mma_kernel,
                         cudaFuncAttributeMaxDynamicSharedMemorySize, SM_TOTAL);

    embed_kernel<<<(N_NODES * 32 + 255) / 256, 256>>>(x, type_emb, output_emb, hA);

    // ---- build CSR for both relations (edges constant across layers) ----
    const int NB = (N_NODES + 255) / 256;   // 391
    const int* eis[2] = { e_pos, e_inv };
    for (int rel = 0; rel < 2; rel++) {
        int* rp = rowptr + (size_t)rel * (N_NODES + 1);
        int* cu = cursor + (size_t)rel * N_NODES;
        int* cs = csrsrc + (size_t)rel * N_EDGES;
        int* bs = bsums + (size_t)rel * 512;
        cudaMemsetAsync(rp, 0, (N_NODES + 1) * sizeof(int));
        hist_kernel<<<(N_EDGES + 255) / 256, 256>>>(eis[rel], rp);
        scan1_kernel<<<NB, 256>>>(rp, bs);
        scan2_kernel<<<1, 512>>>(bs, NB);
        scan3_kernel<<<NB, 256>>>(rp, bs);
        cudaMemcpyAsync(cu, rp, N_NODES * sizeof(int), cudaMemcpyDeviceToDevice);
        fill_kernel<<<(N_EDGES + 255) / 256, 256>>>(eis[rel], cu, cs);
    }

    float* h  = hA;
    float* hn = hB;
    const int gemm_grid = (N_NODES + 127) / 128;   // 782
    const int gather_grid = (N_NODES * 32 + 255) / 256;

    for (int l = 0; l < NUM_LAYER; l++) {
        gather_kernel<<<gather_grid, 256>>>(h, rowptr, csrsrc, i0);
        gather_kernel<<<gather_grid, 256>>>(h, rowptr + (N_NODES + 1),
                                            csrsrc + N_EDGES, i1);

        const float* w1p0 = l1w + (size_t)(l * 2 + 0) * D * D;
        const float* w1p1 = l1w + (size_t)(l * 2 + 1) * D * D;
        const float* w2p0 = l2w + (size_t)(l * 2 + 0) * D * D;
        const float* w2p1 = l2w + (size_t)(l * 2 + 1) * D * D;
        const float* b1p0 = l1b + (size_t)(l * 2 + 0) * D;
        const float* b1p1 = l1b + (size_t)(l * 2 + 1) * D;
        const float* b2p0 = l2b + (size_t)(l * 2 + 0) * D;
        const float* b2p1 = l2b + (size_t)(l * 2 + 1) * D;

        gin_mma_kernel<<<gemm_grid, 256, SM_TOTAL>>>(
            i0, w1p0, b1p0, w2p0, b2p0, hn, /*accumulate=*/0, /*relu_out=*/0);
        gin_mma_kernel<<<gemm_grid, 256, SM_TOTAL>>>(
            i1, w1p1, b1p1, w2p1, b2p1, hn, /*accumulate=*/1,
            /*relu_out=*/(l < NUM_LAYER - 1) ? 1 : 0);

        float* tmp = h; h = hn; hn = tmp;
    }

    bounds_kernel<<<1, NGRAPH + 1>>>(batch);
    pool_kernel<<<NGRAPH, D>>>(h, out, out_size);
}